// round 1
// baseline (speedup 1.0000x reference)
#include <cuda_runtime.h>
#include <cuda_bf16.h>
#include <math.h>

// Problem constants
#define B_ 4
#define S_ 2048
#define DIN 2048
#define DOUT 2048
#define DEPTH 11
#define NLEV (DEPTH + 1)          // 12 levels
#define NNODES 4095               // 2^(DEPTH+1)-1
#define NTOK (B_ * S_)            // 8192 tokens

// Scratch for transposed w_out: [NNODES, DOUT] row-major (32.0 MiB + pad)
__device__ float g_wout_t[(size_t)NNODES * DOUT];

// ---------------------------------------------------------------------------
// Kernel 1: transpose w_out [DOUT, NNODES] -> g_wout_t [NNODES, DOUT]
// ---------------------------------------------------------------------------
__global__ void wout_transpose_kernel(const float* __restrict__ w_out) {
    __shared__ float tile[32][33];
    const int nx0 = blockIdx.x * 32;   // node dim (cols of w_out)
    const int dy0 = blockIdx.y * 32;   // dout dim (rows of w_out)
    const int tx = threadIdx.x;        // 0..31
    const int ty = threadIdx.y;        // 0..7

#pragma unroll
    for (int j = 0; j < 32; j += 8) {
        int r = dy0 + ty + j;          // dout row
        int c = nx0 + tx;              // node col
        float v = 0.0f;
        if (c < NNODES) v = w_out[(size_t)r * NNODES + c];
        tile[ty + j][tx] = v;
    }
    __syncthreads();
#pragma unroll
    for (int j = 0; j < 32; j += 8) {
        int r = nx0 + ty + j;          // node row of transposed
        int c = dy0 + tx;              // dout col
        if (r < NNODES) g_wout_t[(size_t)r * DOUT + c] = tile[tx][ty + j];
    }
}

// ---------------------------------------------------------------------------
// Kernel 2: FFF — one warp per token.
//   Phase 1: traverse the tree (12 data-dependent dot products, warp-reduced).
//   Phase 2: out = sum_l gelu(score_l) * w_out_T[node_l].
// ---------------------------------------------------------------------------
__device__ __forceinline__ float gelu_exact(float s) {
    // torch nn.GELU default (erf form)
    return 0.5f * s * (1.0f + erff(s * 0.70710678118654752440f));
}

__global__ __launch_bounds__(256) void fff_kernel(
    const float* __restrict__ x,
    const float* __restrict__ w_in,
    const float* __restrict__ wout_t,
    float* __restrict__ out)
{
    const int warp = (blockIdx.x * blockDim.x + threadIdx.x) >> 5;
    const int lane = threadIdx.x & 31;
    if (warp >= NTOK) return;

    // ---- Load x row into registers: 16 x float4 per lane (coalesced) ----
    const float4* __restrict__ xr4 = reinterpret_cast<const float4*>(x + (size_t)warp * DIN);
    float4 xr[16];
#pragma unroll
    for (int i = 0; i < 16; i++) xr[i] = xr4[i * 32 + lane];

    // ---- Phase 1: tree traversal ----
    int   nodes[NLEV];
    float g[NLEV];
    int cur = 0;
#pragma unroll
    for (int l = 0; l < NLEV; l++) {
        const float4* __restrict__ w = reinterpret_cast<const float4*>(w_in + (size_t)cur * DIN);
        float p = 0.0f;
#pragma unroll
        for (int i = 0; i < 16; i++) {
            float4 wv = w[i * 32 + lane];
            p += xr[i].x * wv.x;
            p += xr[i].y * wv.y;
            p += xr[i].z * wv.z;
            p += xr[i].w * wv.w;
        }
        // butterfly reduce — all lanes end with the full sum
#pragma unroll
        for (int off = 16; off > 0; off >>= 1)
            p += __shfl_xor_sync(0xffffffffu, p, off);

        nodes[l] = cur;
        g[l] = gelu_exact(p);
        cur = cur * 2 + (p >= 0.0f ? 2 : 1);
    }

    // ---- Phase 2: accumulate output (x registers are dead; reuse RF) ----
    float4 acc[16];
#pragma unroll
    for (int i = 0; i < 16; i++) acc[i] = make_float4(0.f, 0.f, 0.f, 0.f);

#pragma unroll
    for (int l = 0; l < NLEV; l++) {
        const float4* __restrict__ w = reinterpret_cast<const float4*>(wout_t + (size_t)nodes[l] * DOUT);
        const float gl = g[l];
#pragma unroll
        for (int i = 0; i < 16; i++) {
            float4 wv = w[i * 32 + lane];
            acc[i].x += gl * wv.x;
            acc[i].y += gl * wv.y;
            acc[i].z += gl * wv.z;
            acc[i].w += gl * wv.w;
        }
    }

    float4* __restrict__ o = reinterpret_cast<float4*>(out + (size_t)warp * DOUT);
#pragma unroll
    for (int i = 0; i < 16; i++) o[i * 32 + lane] = acc[i];
}

// ---------------------------------------------------------------------------
// kernel_launch
//   inputs (metadata order): x [B,S,DIN] f32, w_in [NNODES,DIN] f32,
//                            w_out [DOUT,NNODES] f32
//   output: [B,S,DOUT] f32
// ---------------------------------------------------------------------------
extern "C" void kernel_launch(void* const* d_in, const int* in_sizes, int n_in,
                              void* d_out, int out_size) {
    const float* x     = (const float*)d_in[0];
    const float* w_in  = (const float*)d_in[1];
    const float* w_out = (const float*)d_in[2];
    float* out = (float*)d_out;

    float* wout_t;
    cudaGetSymbolAddress((void**)&wout_t, g_wout_t);

    // Transpose w_out -> g_wout_t
    {
        dim3 blk(32, 8);
        dim3 grd((NNODES + 31) / 32, DOUT / 32);
        wout_transpose_kernel<<<grd, blk>>>(w_out);
    }

    // FFF: one warp per token, 8 warps per CTA
    {
        const int threads = 256;
        const int warps_per_cta = threads / 32;
        const int blocks = (NTOK + warps_per_cta - 1) / warps_per_cta;
        fff_kernel<<<blocks, threads>>>(x, w_in, wout_t, out);
    }
}

// round 2
// speedup vs baseline: 1.0158x; 1.0158x over previous
#include <cuda_runtime.h>
#include <cuda_bf16.h>
#include <math.h>

// Problem constants
#define B_ 4
#define S_ 2048
#define DIN 2048
#define DOUT 2048
#define DEPTH 11
#define NLEV (DEPTH + 1)          // 12 levels
#define NNODES 4095               // 2^(DEPTH+1)-1
#define NTOK (B_ * S_)            // 8192 tokens
#define NLEAF 2048                // leaves are nodes [2047, 4094]
#define LEAF0 2047

// Static scratch (allocation-free rule)
__device__ float          g_wout_t[(size_t)NNODES * DOUT];   // transposed w_out
__device__ float          g_gel[NTOK * NLEV];                // gelu(score) per token/level
__device__ unsigned short g_nodes[NTOK * NLEV];              // node id per token/level
__device__ int            g_hist[NLEAF];                     // leaf histogram
__device__ int            g_base[NLEAF];                     // exclusive-scan offsets
__device__ int            g_perm[NTOK];                      // leaf-sorted token order

// ---------------------------------------------------------------------------
// Transpose w_out [DOUT, NNODES] -> g_wout_t [NNODES, DOUT]
// ---------------------------------------------------------------------------
__global__ void wout_transpose_kernel(const float* __restrict__ w_out) {
    __shared__ float tile[32][33];
    const int nx0 = blockIdx.x * 32;   // node dim
    const int dy0 = blockIdx.y * 32;   // dout dim
    const int tx = threadIdx.x;
    const int ty = threadIdx.y;
#pragma unroll
    for (int j = 0; j < 32; j += 8) {
        int r = dy0 + ty + j, c = nx0 + tx;
        float v = 0.0f;
        if (c < NNODES) v = w_out[(size_t)r * NNODES + c];
        tile[ty + j][tx] = v;
    }
    __syncthreads();
#pragma unroll
    for (int j = 0; j < 32; j += 8) {
        int r = nx0 + ty + j, c = dy0 + tx;
        if (r < NNODES) g_wout_t[(size_t)r * DOUT + c] = tile[tx][ty + j];
    }
}

__device__ __forceinline__ float gelu_exact(float s) {
    return 0.5f * s * (1.0f + erff(s * 0.70710678118654752440f));
}

// ---------------------------------------------------------------------------
// Phase 1: traversal. One warp per token. Writes (node, gelu) per level and
// builds the leaf histogram.
// ---------------------------------------------------------------------------
__global__ __launch_bounds__(256, 2) void traverse_kernel(
    const float* __restrict__ x,
    const float* __restrict__ w_in)
{
    const int warp = (blockIdx.x * blockDim.x + threadIdx.x) >> 5;
    const int lane = threadIdx.x & 31;
    if (warp >= NTOK) return;

    const float4* __restrict__ xr4 = reinterpret_cast<const float4*>(x + (size_t)warp * DIN);
    float4 xr[16];
#pragma unroll
    for (int i = 0; i < 16; i++) xr[i] = xr4[i * 32 + lane];

    int cur = 0;
#pragma unroll
    for (int l = 0; l < NLEV; l++) {
        const float4* __restrict__ w = reinterpret_cast<const float4*>(w_in + (size_t)cur * DIN);
        float p0 = 0.f, p1 = 0.f, p2 = 0.f, p3 = 0.f;
#pragma unroll
        for (int i = 0; i < 16; i += 4) {
            float4 a = w[(i + 0) * 32 + lane];
            float4 b = w[(i + 1) * 32 + lane];
            float4 c = w[(i + 2) * 32 + lane];
            float4 d = w[(i + 3) * 32 + lane];
            p0 += xr[i + 0].x * a.x + xr[i + 0].y * a.y + xr[i + 0].z * a.z + xr[i + 0].w * a.w;
            p1 += xr[i + 1].x * b.x + xr[i + 1].y * b.y + xr[i + 1].z * b.z + xr[i + 1].w * b.w;
            p2 += xr[i + 2].x * c.x + xr[i + 2].y * c.y + xr[i + 2].z * c.z + xr[i + 2].w * c.w;
            p3 += xr[i + 3].x * d.x + xr[i + 3].y * d.y + xr[i + 3].z * d.z + xr[i + 3].w * d.w;
        }
        float p = (p0 + p1) + (p2 + p3);
#pragma unroll
        for (int off = 16; off > 0; off >>= 1)
            p += __shfl_xor_sync(0xffffffffu, p, off);

        if (lane == 0) {
            g_nodes[warp * NLEV + l] = (unsigned short)cur;
            g_gel[warp * NLEV + l]   = gelu_exact(p);
        }
        cur = cur * 2 + (p >= 0.0f ? 2 : 1);
    }
    // after the loop, the level-11 node visited is nodes[11]; its value was
    // stored above. Leaf bucket = nodes[11] - LEAF0.
    if (lane == 0) {
        int leaf = (cur - 1) >> 1;          // recover nodes[11] = parent of cur
        atomicAdd(&g_hist[leaf - LEAF0], 1);
    }
}

// ---------------------------------------------------------------------------
// Exclusive scan of g_hist[2048] -> g_base. One CTA, Hillis-Steele ping-pong.
// ---------------------------------------------------------------------------
__global__ __launch_bounds__(1024) void scan_kernel() {
    __shared__ int s0[NLEAF];
    __shared__ int s1[NLEAF];
    const int t = threadIdx.x;
    s0[t] = g_hist[t];
    s0[t + 1024] = g_hist[t + 1024];
    __syncthreads();
    int* src = s0; int* dst = s1;
    for (int off = 1; off < NLEAF; off <<= 1) {
#pragma unroll
        for (int k = 0; k < 2; k++) {
            int i = t + k * 1024;
            int v = src[i];
            if (i >= off) v += src[i - off];
            dst[i] = v;
        }
        __syncthreads();
        int* tmp = src; src = dst; dst = tmp;
    }
    // src holds inclusive scan; write exclusive
    g_base[t]        = (t == 0) ? 0 : src[t - 1];
    g_base[t + 1024] = src[t + 1023];
}

// ---------------------------------------------------------------------------
// Scatter: token -> leaf-sorted position
// ---------------------------------------------------------------------------
__global__ __launch_bounds__(256) void scatter_kernel() {
    int t = blockIdx.x * blockDim.x + threadIdx.x;
    if (t >= NTOK) return;
    int leaf = (int)g_nodes[t * NLEV + DEPTH];   // level-11 node
    int pos = atomicAdd(&g_base[leaf - LEAF0], 1);
    g_perm[pos] = t;
}

// ---------------------------------------------------------------------------
// Phase 2: accumulate. One warp per (sorted) token.
// Consecutive warps handle same-leaf tokens -> their 12 gathered rows hit L1.
// ---------------------------------------------------------------------------
__global__ __launch_bounds__(256, 2) void accum_kernel(float* __restrict__ out) {
    const int widx = (blockIdx.x * blockDim.x + threadIdx.x) >> 5;
    const int lane = threadIdx.x & 31;
    if (widx >= NTOK) return;
    const int tok = g_perm[widx];

    float4 acc[16];
#pragma unroll
    for (int i = 0; i < 16; i++) acc[i] = make_float4(0.f, 0.f, 0.f, 0.f);

#pragma unroll
    for (int l = 0; l < NLEV; l++) {
        const int   node = (int)g_nodes[tok * NLEV + l];
        const float gl   = g_gel[tok * NLEV + l];
        const float4* __restrict__ w =
            reinterpret_cast<const float4*>(g_wout_t + (size_t)node * DOUT);
#pragma unroll
        for (int i = 0; i < 16; i++) {
            float4 wv = w[i * 32 + lane];
            acc[i].x += gl * wv.x;
            acc[i].y += gl * wv.y;
            acc[i].z += gl * wv.z;
            acc[i].w += gl * wv.w;
        }
    }

    float4* __restrict__ o = reinterpret_cast<float4*>(out + (size_t)tok * DOUT);
#pragma unroll
    for (int i = 0; i < 16; i++) o[i * 32 + lane] = acc[i];
}

// ---------------------------------------------------------------------------
// kernel_launch: transpose || traverse -> memset hist... order:
//   memset(hist) -> transpose -> traverse -> scan -> scatter -> accum
// ---------------------------------------------------------------------------
extern "C" void kernel_launch(void* const* d_in, const int* in_sizes, int n_in,
                              void* d_out, int out_size) {
    const float* x     = (const float*)d_in[0];
    const float* w_in  = (const float*)d_in[1];
    const float* w_out = (const float*)d_in[2];
    float* out = (float*)d_out;

    void* hist_ptr;
    cudaGetSymbolAddress(&hist_ptr, g_hist);
    cudaMemsetAsync(hist_ptr, 0, NLEAF * sizeof(int));

    {   // transpose w_out
        dim3 blk(32, 8);
        dim3 grd((NNODES + 31) / 32, DOUT / 32);
        wout_transpose_kernel<<<grd, blk>>>(w_out);
    }
    {   // phase 1 traversal
        const int threads = 256;
        const int blocks = (NTOK * 32 + threads - 1) / threads;
        traverse_kernel<<<blocks, threads>>>(x, w_in);
    }
    scan_kernel<<<1, 1024>>>();
    scatter_kernel<<<(NTOK + 255) / 256, 256>>>();
    {   // phase 2 accumulate
        const int threads = 256;
        const int blocks = (NTOK * 32 + threads - 1) / threads;
        accum_kernel<<<blocks, threads>>>(out);
    }
}